// round 8
// baseline (speedup 1.0000x reference)
#include <cuda_runtime.h>
#include <cstdint>

#define K 128
#define AT_NB 16
#define Z_NB 16

typedef unsigned long long ull;

// ---------------- persistent device scratch (no allocs allowed) ----------------
__device__ float g_A[K * K];      // A[i][j] = sum_o Wq[o,i]*Wk[o,j] / sqrt(128)
__device__ float g_M0[K * K];     // transposed [k][o]: inv_sqrt2*scale[o]*sum_c conv_w[o,c]*Wv[c,k]
__device__ float g_M1[K * K];     // transposed [k][o]: same with conv_w[o,128+c]
__device__ float g_tb[K];         // (conv_b-mean)*scale + beta
__device__ float g_w[65536 * 4];  // attention weights per (b,s)

// ---------------- packed f32x2 helpers ----------------
__device__ __forceinline__ ull pack_dup(float v) {
    unsigned u = __float_as_uint(v);
    ull r;
    asm("mov.b64 %0, {%1, %1};" : "=l"(r) : "r"(u));
    return r;
}
__device__ __forceinline__ void fma2(ull& acc, ull a, ull b) {
    asm("fma.rn.f32x2 %0, %1, %2, %0;" : "+l"(acc) : "l"(a), "l"(b));
}
__device__ __forceinline__ float f2lo(ull v) { return __uint_as_float((unsigned)v); }
__device__ __forceinline__ float f2hi(ull v) { return __uint_as_float((unsigned)(v >> 32)); }

// ---------------- setup: build A, M0t, M1t, tb ----------------
__global__ void setup_kernel(const float* __restrict__ Wq, const float* __restrict__ Wk,
                             const float* __restrict__ Wv, const float* __restrict__ conv_w,
                             const float* __restrict__ conv_b, const float* __restrict__ gamma,
                             const float* __restrict__ beta, const float* __restrict__ mean,
                             const float* __restrict__ var) {
    const int m = blockIdx.y;   // 0: A, 1: M0, 2: M1
    const int r = blockIdx.x;   // row index (i for A, o for M)
    const int t = threadIdx.x;  // 128 threads
    if (m == 0) {
        float acc = 0.f;
        for (int o = 0; o < K; ++o)
            acc += Wq[o * K + r] * Wk[o * K + t];
        g_A[r * K + t] = acc * 0.08838834764831845f;  // 1/sqrt(128)
    } else {
        __shared__ float cw[K];
        const float* src = conv_w + r * 256 + (m == 2 ? K : 0);
        cw[t] = src[t];
        __syncthreads();
        const float sc = gamma[r] * rsqrtf(var[r] + 1e-5f);
        float acc = 0.f;
        for (int c = 0; c < K; ++c)
            acc += cw[c] * Wv[c * K + t];
        const float val = acc * sc * 0.7071067811865476f;
        if (m == 1) {
            g_M0[t * K + r] = val;
            if (t == 0) g_tb[r] = (conv_b[r] - mean[r]) * sc + beta[r];
        } else {
            g_M1[t * K + r] = val;
        }
    }
}

// ---------------- attention weights: p = y@A, dots, softmax -> g_w ----------------
__global__ __launch_bounds__(256) void attn_kernel(const float* __restrict__ x,
                                                   const float* __restrict__ y, int B) {
    extern __shared__ float sm[];
    float* sA = sm;                // K*K       = 16384 floats
    float* sY = sA + K * K;        // AT_NB*K   =  2048
    float* sP = sY + AT_NB * K;    // AT_NB*K   =  2048
    float* sD = sP + AT_NB * K;    // AT_NB*16  =   256
    const int t = threadIdx.x;

    for (int i = t; i < K * K / 4; i += 256)
        ((float4*)sA)[i] = ((const float4*)g_A)[i];

    const int nchunk = B / AT_NB;
    for (int ch = blockIdx.x; ch < nchunk; ch += gridDim.x) {
        const int b0 = ch * AT_NB;
        __syncthreads();  // protect sY/sP/sA from reuse across iterations
        for (int i = t; i < AT_NB * K / 4; i += 256)
            ((float4*)sY)[i] = ((const float4*)(y + (size_t)b0 * K))[i];
        __syncthreads();

        // P = Y @ A : thread -> 4 j's (packed as 2 f32x2 lanes) x 2 b's
        {
            const int jj = (t & 31) * 4;
            const int bb0 = (t >> 5) * 2;
            ull a0x = 0, a0y = 0, a1x = 0, a1y = 0;
            const float* y0p = sY + bb0 * K;
            const float* y1p = y0p + K;
            for (int i = 0; i < K; ++i) {
                const ulonglong2 av = *(const ulonglong2*)(sA + i * K + jj);
                const ull Y0 = pack_dup(y0p[i]);
                const ull Y1 = pack_dup(y1p[i]);
                fma2(a0x, av.x, Y0);
                fma2(a0y, av.y, Y0);
                fma2(a1x, av.x, Y1);
                fma2(a1y, av.y, Y1);
            }
            ull* pp0 = (ull*)(sP + bb0 * K + jj);
            pp0[0] = a0x;
            pp0[1] = a0y;
            ull* pp1 = (ull*)(sP + (bb0 + 1) * K + jj);
            pp1[0] = a1x;
            pp1[1] = a1y;
        }
        __syncthreads();

        // partial dots: dot[bb][s] = p . x_s   (4 partials per dot)
        {
            const int q = t >> 2, part = t & 3;
            const int bb = q >> 2, s = q & 3;
            const float4* xr = (const float4*)(x + (((size_t)(b0 + bb)) * 4 + s) * K + part * 32);
            const float4* pr = (const float4*)(sP + bb * K + part * 32);
            float acc = 0.f;
#pragma unroll
            for (int j = 0; j < 8; ++j) {
                const float4 xv = xr[j];
                const float4 pv = pr[j];
                acc += xv.x * pv.x + xv.y * pv.y + xv.z * pv.z + xv.w * pv.w;
            }
            sD[q * 4 + part] = acc;
        }
        __syncthreads();

        if (t < AT_NB) {
            float dd[4];
#pragma unroll
            for (int s = 0; s < 4; ++s) {
                const float* p = sD + (t * 4 + s) * 4;
                dd[s] = (p[0] + p[1]) + (p[2] + p[3]);
            }
            const float mx = fmaxf(fmaxf(dd[0], dd[1]), fmaxf(dd[2], dd[3]));
            float e[4];
            float es = 0.f;
#pragma unroll
            for (int s = 0; s < 4; ++s) {
                e[s] = expf(dd[s] - mx);
                es += e[s];
            }
            const float inv = 1.f / es;
            float* wp = g_w + (size_t)(b0 + t) * 4;
#pragma unroll
            for (int s = 0; s < 4; ++s) wp[s] = e[s] * inv;
        }
    }
}

// ---------------- main z kernel: c-vectors + fused GEMV + BN + leaky ----------------
__global__ __launch_bounds__(512) void z_kernel(const float* __restrict__ x,
                                                float* __restrict__ out, int B) {
    extern __shared__ float sm[];
    float* sM0 = sm;                          // 16384 floats
    float* sM1 = sM0 + K * K;                 // 16384 floats
    float2* sCA = (float2*)(sM1 + K * K);     // Z_NB*K float2 (c0,c1)
    float2* sCB = sCA + Z_NB * K;             // Z_NB*K float2 (c2,c3)
    const int t = threadIdx.x;  // 512

    for (int i = t; i < K * K / 4; i += 512) {
        ((float4*)sM0)[i] = ((const float4*)g_M0)[i];
        ((float4*)sM1)[i] = ((const float4*)g_M1)[i];
    }
    const int o = t & 127;
    const int bbg = t >> 7;  // 0..3, each handles 4 consecutive b's
    const float tb = g_tb[o];

    const int nchunk = B / Z_NB;
    for (int ch = blockIdx.x; ch < nchunk; ch += gridDim.x) {
        const int b0 = ch * Z_NB;
        __syncthreads();
        // form c vectors: cA=(w0x0+w1x1, w0x0-w1x1), cB=(w2x2+w3x3, w2x2-w3x3)
        for (int idx = t; idx < Z_NB * K; idx += 512) {
            const int bb = idx >> 7, k = idx & 127;
            const float* xp = x + ((size_t)(b0 + bb)) * (4 * K) + k;
            const float x0 = xp[0], x1 = xp[K], x2 = xp[2 * K], x3 = xp[3 * K];
            const float* wp = g_w + (size_t)(b0 + bb) * 4;
            const float a0 = wp[0] * x0, a1 = wp[1] * x1;
            const float a2 = wp[2] * x2, a3 = wp[3] * x3;
            sCA[idx] = make_float2(a0 + a1, a0 - a1);
            sCB[idx] = make_float2(a2 + a3, a2 - a3);
        }
        __syncthreads();

        ull acc[4] = {0ull, 0ull, 0ull, 0ull};
        const float2* cA = sCA + (bbg * 4) * K;
        const float2* cB = sCB + (bbg * 4) * K;
        for (int k = 0; k < K; k += 4) {
            const float* m0p = sM0 + k * K + o;
            const float* m1p = sM1 + k * K + o;
            const ull M00 = pack_dup(m0p[0]);
            const ull M01 = pack_dup(m0p[K]);
            const ull M02 = pack_dup(m0p[2 * K]);
            const ull M03 = pack_dup(m0p[3 * K]);
            const ull M10 = pack_dup(m1p[0]);
            const ull M11 = pack_dup(m1p[K]);
            const ull M12 = pack_dup(m1p[2 * K]);
            const ull M13 = pack_dup(m1p[3 * K]);
#pragma unroll
            for (int i = 0; i < 4; ++i) {
                const ulonglong2* pa = (const ulonglong2*)(cA + i * K + k);
                const ulonglong2* pb = (const ulonglong2*)(cB + i * K + k);
                const ulonglong2 va0 = pa[0];
                const ulonglong2 va1 = pa[1];
                const ulonglong2 vb0 = pb[0];
                const ulonglong2 vb1 = pb[1];
                fma2(acc[i], M00, va0.x);
                fma2(acc[i], M01, va0.y);
                fma2(acc[i], M02, va1.x);
                fma2(acc[i], M03, va1.y);
                fma2(acc[i], M10, vb0.x);
                fma2(acc[i], M11, vb0.y);
                fma2(acc[i], M12, vb1.x);
                fma2(acc[i], M13, vb1.y);
            }
        }

        // epilogue: bias + leaky relu, write 8 consecutive j's (one 32B sector)
        float vals[8];
#pragma unroll
        for (int i = 0; i < 4; ++i) {
            float ze = f2lo(acc[i]) + tb;
            float zo = f2hi(acc[i]) + tb;
            ze = ze > 0.f ? ze : 0.01f * ze;
            zo = zo > 0.f ? zo : 0.01f * zo;
            vals[2 * i] = ze;
            vals[2 * i + 1] = zo;
        }
        const int b0g = b0 + bbg * 4;
        const int g = b0g >> 9;        // / 512
        const int d0 = b0g & 511;
        float* op = out + ((size_t)g * K + o) * 1024 + 2 * d0;
        ((float4*)op)[0] = make_float4(vals[0], vals[1], vals[2], vals[3]);
        ((float4*)op)[1] = make_float4(vals[4], vals[5], vals[6], vals[7]);
    }
}

// ---------------- launch ----------------
extern "C" void kernel_launch(void* const* d_in, const int* in_sizes, int n_in,
                              void* d_out, int out_size) {
    const float* x = (const float*)d_in[0];
    const float* y = (const float*)d_in[1];
    const float* Wq = (const float*)d_in[2];
    const float* Wk = (const float*)d_in[3];
    const float* Wv = (const float*)d_in[4];
    const float* conv_w = (const float*)d_in[5];
    const float* conv_b = (const float*)d_in[6];
    const float* gamma = (const float*)d_in[7];
    const float* beta = (const float*)d_in[8];
    const float* mean = (const float*)d_in[9];
    const float* var = (const float*)d_in[10];
    const int B = in_sizes[0] / (4 * K);

    const size_t attn_smem = (size_t)(K * K + AT_NB * K * 2 + AT_NB * 16) * sizeof(float);
    const size_t z_smem = (size_t)(2 * K * K) * sizeof(float) + (size_t)(2 * Z_NB * K) * sizeof(float2);
    cudaFuncSetAttribute(attn_kernel, cudaFuncAttributeMaxDynamicSharedMemorySize, (int)attn_smem);
    cudaFuncSetAttribute(z_kernel, cudaFuncAttributeMaxDynamicSharedMemorySize, (int)z_smem);

    setup_kernel<<<dim3(K, 3), K>>>(Wq, Wk, Wv, conv_w, conv_b, gamma, beta, mean, var);
    attn_kernel<<<296, 256, attn_smem>>>(x, y, B);
    z_kernel<<<148, 512, z_smem>>>(x, (float*)d_out, B);
}